// round 1
// baseline (speedup 1.0000x reference)
#include <cuda_runtime.h>

// Bilinear table interpolation:
//   inputs: d_in[0] = points [N,2] fp32 (x, v), d_in[1] = grid [1024,1024] fp32,
//           d_in[2] = bounds [2,2] fp32 [[x_lo,x_hi],[v_lo,v_hi]]
//   output: d_out = [N] fp32 (shaped [1,N,1] by the reference)

#define GRID_W 1024
#define GRID_H 1024

__device__ __forceinline__ float interp_one(float px, float pv,
                                            float oy, float sy,
                                            float ox, float sx,
                                            const float* __restrict__ g) {
    // normalized fractional indices
    float qy = (px - oy) * sy;   // row coordinate (dim0)
    float qx = (pv - ox) * sx;   // col coordinate (dim1)

    // floor clamped to [0, size-2], alpha clamped to [0, 1]
    float fy = fminf(fmaxf(floorf(qy), 0.0f), (float)(GRID_H - 2));
    float fx = fminf(fmaxf(floorf(qx), 0.0f), (float)(GRID_W - 2));
    float ay = fminf(fmaxf(qy - fy, 0.0f), 1.0f);
    float ax = fminf(fmaxf(qx - fx, 0.0f), 1.0f);

    int y0 = (int)fy;
    int x0 = (int)fx;
    int idx = (y0 << 10) + x0;   // GRID_W == 1024

    float tl = __ldg(g + idx);
    float tr = __ldg(g + idx + 1);
    float bl = __ldg(g + idx + GRID_W);
    float br = __ldg(g + idx + GRID_W + 1);

    float top = fmaf(tr - tl, ax, tl);
    float bot = fmaf(br - bl, ax, bl);
    return fmaf(bot - top, ay, top);
}

__global__ void tableInterp_kernel(const float4* __restrict__ pts,  // [N/2] float4 = 2 points each
                                   const float* __restrict__ grid,
                                   const float* __restrict__ bounds,
                                   float* __restrict__ out,
                                   int n_quads) {                   // N/4
    int i = blockIdx.x * blockDim.x + threadIdx.x;
    if (i >= n_quads) return;

    // bounds: uniform loads, L1 broadcast
    float x_lo = __ldg(bounds + 0);
    float x_hi = __ldg(bounds + 1);
    float v_lo = __ldg(bounds + 2);
    float v_hi = __ldg(bounds + 3);
    float sy = (float)(GRID_H - 1) / (x_hi - x_lo);
    float sx = (float)(GRID_W - 1) / (v_hi - v_lo);

    // 4 points per thread: two float4 loads
    float4 p01 = pts[2 * i];
    float4 p23 = pts[2 * i + 1];

    float4 r;
    r.x = interp_one(p01.x, p01.y, x_lo, sy, v_lo, sx, grid);
    r.y = interp_one(p01.z, p01.w, x_lo, sy, v_lo, sx, grid);
    r.z = interp_one(p23.x, p23.y, x_lo, sy, v_lo, sx, grid);
    r.w = interp_one(p23.z, p23.w, x_lo, sy, v_lo, sx, grid);

    reinterpret_cast<float4*>(out)[i] = r;
}

extern "C" void kernel_launch(void* const* d_in, const int* in_sizes, int n_in,
                              void* d_out, int out_size) {
    const float4* pts   = (const float4*)d_in[0];
    const float*  grid  = (const float*)d_in[1];
    const float*  bnds  = (const float*)d_in[2];
    float*        out   = (float*)d_out;

    int n = in_sizes[0] / 2;        // number of points (inputs is [N,2])
    int n_quads = n / 4;            // 4 points per thread (N = 4194304, divisible)

    int threads = 256;
    int blocks = (n_quads + threads - 1) / threads;
    tableInterp_kernel<<<blocks, threads>>>(pts, grid, bnds, out, n_quads);
}

// round 2
// speedup vs baseline: 1.0844x; 1.0844x over previous
#include <cuda_runtime.h>

// Bilinear table interpolation, R2: LDG.128 row-pair gathers to cut L1tex wavefronts.
//   d_in[0] = points [N,2] fp32 (x, v)
//   d_in[1] = grid [1024,1024] fp32
//   d_in[2] = bounds [2,2] fp32
//   d_out   = [N] fp32

#define GRID_W 1024
#define GRID_H 1024

// Load the horizontally-adjacent pair (g[row*W + x0], g[row*W + x0 + 1]) with
// one aligned 16B load (covers the pair when x0%4 < 3) plus a predicated
// scalar load for the x0%4 == 3 case.
__device__ __forceinline__ float2 load_pair(const float* __restrict__ g,
                                             int rowbase, int x0) {
    int a = x0 & ~3;
    int r = x0 & 3;
    float4 q = __ldg(reinterpret_cast<const float4*>(g + rowbase + a));
    float extra = 0.0f;
    if (r == 3) extra = __ldg(g + rowbase + x0 + 1);   // predicated, ~25% of lanes

    float lo_half_l = (r & 1) ? q.y : q.x;
    float hi_half_l = (r & 1) ? q.w : q.z;
    float tl = (r & 2) ? hi_half_l : lo_half_l;

    float lo_half_r = (r & 1) ? q.z : q.y;
    float hi_half_r = (r & 1) ? extra : q.w;
    float tr = (r & 2) ? hi_half_r : lo_half_r;

    return make_float2(tl, tr);
}

__device__ __forceinline__ float interp_one(float px, float pv,
                                            float oy, float sy,
                                            float ox, float sx,
                                            const float* __restrict__ g) {
    float qy = (px - oy) * sy;   // row coordinate (dim0)
    float qx = (pv - ox) * sx;   // col coordinate (dim1)

    float fy = fminf(fmaxf(floorf(qy), 0.0f), (float)(GRID_H - 2));
    float fx = fminf(fmaxf(floorf(qx), 0.0f), (float)(GRID_W - 2));
    float ay = fminf(fmaxf(qy - fy, 0.0f), 1.0f);
    float ax = fminf(fmaxf(qx - fx, 0.0f), 1.0f);

    int y0 = (int)fy;
    int x0 = (int)fx;
    int rowbase = y0 << 10;      // GRID_W == 1024

    float2 t = load_pair(g, rowbase, x0);            // tl, tr
    float2 b = load_pair(g, rowbase + GRID_W, x0);   // bl, br

    float top = fmaf(t.y - t.x, ax, t.x);
    float bot = fmaf(b.y - b.x, ax, b.x);
    return fmaf(bot - top, ay, top);
}

__global__ void tableInterp_kernel(const float4* __restrict__ pts,
                                   const float* __restrict__ grid,
                                   const float* __restrict__ bounds,
                                   float* __restrict__ out,
                                   int n_quads) {
    int i = blockIdx.x * blockDim.x + threadIdx.x;
    if (i >= n_quads) return;

    float x_lo = __ldg(bounds + 0);
    float x_hi = __ldg(bounds + 1);
    float v_lo = __ldg(bounds + 2);
    float v_hi = __ldg(bounds + 3);
    float sy = (float)(GRID_H - 1) / (x_hi - x_lo);
    float sx = (float)(GRID_W - 1) / (v_hi - v_lo);

    float4 p01 = pts[2 * i];
    float4 p23 = pts[2 * i + 1];

    float4 r;
    r.x = interp_one(p01.x, p01.y, x_lo, sy, v_lo, sx, grid);
    r.y = interp_one(p01.z, p01.w, x_lo, sy, v_lo, sx, grid);
    r.z = interp_one(p23.x, p23.y, x_lo, sy, v_lo, sx, grid);
    r.w = interp_one(p23.z, p23.w, x_lo, sy, v_lo, sx, grid);

    reinterpret_cast<float4*>(out)[i] = r;
}

extern "C" void kernel_launch(void* const* d_in, const int* in_sizes, int n_in,
                              void* d_out, int out_size) {
    const float4* pts  = (const float4*)d_in[0];
    const float*  grid = (const float*)d_in[1];
    const float*  bnds = (const float*)d_in[2];
    float*        out  = (float*)d_out;

    int n = in_sizes[0] / 2;   // number of points ([N,2])
    int n_quads = n / 4;       // 4 points per thread

    int threads = 256;
    int blocks = (n_quads + threads - 1) / threads;
    tableInterp_kernel<<<blocks, threads>>>(pts, grid, bnds, out, n_quads);
}

// round 3
// speedup vs baseline: 1.6663x; 1.5366x over previous
#include <cuda_runtime.h>

// R3: precomputed quad table -> single LDG.128 gather per point.
//   d_in[0] = points [N,2] fp32 (x, v)
//   d_in[1] = grid [1024,1024] fp32
//   d_in[2] = bounds [2,2] fp32
//   d_out   = [N] fp32

#define GRID_W 1024
#define GRID_H 1024
#define QUAD_STRIDE 1024          // row stride of quad table (shift indexing)
#define QUAD_ROWS   (GRID_H - 1)  // 1023 valid y0 rows

// quad[y*1024 + x] = {g[y][x], g[y][x+1], g[y+1][x], g[y+1][x+1]}
// 1023*1024*16B = 16.8 MB static scratch (allowed: __device__ global).
__device__ float4 g_quad[QUAD_ROWS * QUAD_STRIDE];

__global__ void build_quad_kernel(const float* __restrict__ grid) {
    int idx = blockIdx.x * blockDim.x + threadIdx.x;   // one thread per quad
    int total = QUAD_ROWS * (GRID_W - 1);              // 1023 * 1023
    if (idx >= total) return;
    int y = idx / (GRID_W - 1);
    int x = idx - y * (GRID_W - 1);
    int base = (y << 10) + x;
    float4 q;
    q.x = grid[base];
    q.y = grid[base + 1];
    q.z = grid[base + GRID_W];
    q.w = grid[base + GRID_W + 1];
    g_quad[(y << 10) + x] = q;
}

__device__ __forceinline__ float interp_one(float px, float pv,
                                            float oy, float sy,
                                            float ox, float sx) {
    float qy = (px - oy) * sy;   // row coordinate (dim0)
    float qx = (pv - ox) * sx;   // col coordinate (dim1)

    float fy = fminf(fmaxf(floorf(qy), 0.0f), (float)(GRID_H - 2));
    float fx = fminf(fmaxf(floorf(qx), 0.0f), (float)(GRID_W - 2));
    float ay = fminf(fmaxf(qy - fy, 0.0f), 1.0f);
    float ax = fminf(fmaxf(qx - fx, 0.0f), 1.0f);

    int y0 = (int)fy;
    int x0 = (int)fx;

    float4 q = __ldg(&g_quad[(y0 << 10) + x0]);   // {tl, tr, bl, br}

    float top = fmaf(q.y - q.x, ax, q.x);
    float bot = fmaf(q.w - q.z, ax, q.z);
    return fmaf(bot - top, ay, top);
}

__global__ void tableInterp_kernel(const float4* __restrict__ pts,
                                   const float* __restrict__ bounds,
                                   float* __restrict__ out,
                                   int n_quads) {
    int i = blockIdx.x * blockDim.x + threadIdx.x;
    if (i >= n_quads) return;

    float x_lo = __ldg(bounds + 0);
    float x_hi = __ldg(bounds + 1);
    float v_lo = __ldg(bounds + 2);
    float v_hi = __ldg(bounds + 3);
    float sy = (float)(GRID_H - 1) / (x_hi - x_lo);
    float sx = (float)(GRID_W - 1) / (v_hi - v_lo);

    float4 p01 = pts[2 * i];
    float4 p23 = pts[2 * i + 1];

    float4 r;
    r.x = interp_one(p01.x, p01.y, x_lo, sy, v_lo, sx);
    r.y = interp_one(p01.z, p01.w, x_lo, sy, v_lo, sx);
    r.z = interp_one(p23.x, p23.y, x_lo, sy, v_lo, sx);
    r.w = interp_one(p23.z, p23.w, x_lo, sy, v_lo, sx);

    reinterpret_cast<float4*>(out)[i] = r;
}

extern "C" void kernel_launch(void* const* d_in, const int* in_sizes, int n_in,
                              void* d_out, int out_size) {
    const float4* pts  = (const float4*)d_in[0];
    const float*  grid = (const float*)d_in[1];
    const float*  bnds = (const float*)d_in[2];
    float*        out  = (float*)d_out;

    // Build the quad table (every call; deterministic).
    {
        int total = QUAD_ROWS * (GRID_W - 1);
        int threads = 256;
        int blocks = (total + threads - 1) / threads;
        build_quad_kernel<<<blocks, threads>>>(grid);
    }

    int n = in_sizes[0] / 2;   // number of points ([N,2])
    int n_quads = n / 4;       // 4 points per thread

    int threads = 256;
    int blocks = (n_quads + threads - 1) / threads;
    tableInterp_kernel<<<blocks, threads>>>(pts, bnds, out, n_quads);
}